// round 15
// baseline (speedup 1.0000x reference)
#include <cuda_runtime.h>
#include <cuda_fp16.h>
#include <math_constants.h>

#define NNODES 100000
#define NEDGES 1600000
#define HD     64
#define NCLS   10
#define NGRAPH 128
#define CAP    64     // bucket capacity per node (deg ~ Poisson(16); P(>63) ~ 1e-21)

// ---------------- scratch (device globals; no allocations) ----------------
__device__ __align__(16) __half2 g_h16[NNODES * 32];  // h rows, fp16 payload (128B/row)
__device__ __align__(16) float g_abuf[NNODES * HD];   // conv input / output (fp32)
__device__ float g_als[NNODES];
__device__ float g_ald[NNODES];
__device__ int   g_cursor[NNODES];                    // row length after scatter
__device__ int   g_bucket[NNODES * CAP];              // src ids, row n at n*CAP

__device__ __forceinline__ float eluf(float x) {
    return x > 0.f ? x : expm1f(x);
}

// ---------------- bucket init + out zero -----------------------------------
__global__ void k_init(float* __restrict__ out) {
    int i = blockIdx.x * blockDim.x + threadIdx.x;
    if (i < NNODES) {
        g_cursor[i] = 1;               // slot 0 = self loop
        g_bucket[i * CAP] = i;
    }
    if (i < NGRAPH * NCLS) out[i] = 0.f;
}

// ---------------- edge scatter into fixed buckets ---------------------------
// edge_index is INT32 (JAX x64 disabled downgrades jnp.int64 -> int32)
__global__ void k_scatter(const int* __restrict__ ei) {
    int i = (blockIdx.x * blockDim.x + threadIdx.x) * 4;
    if (i >= NEDGES) return;
    int4 s = *(const int4*)(ei + i);
    int4 d = *(const int4*)(ei + NEDGES + i);
    int p0 = atomicAdd(&g_cursor[d.x], 1);
    int p1 = atomicAdd(&g_cursor[d.y], 1);
    int p2 = atomicAdd(&g_cursor[d.z], 1);
    int p3 = atomicAdd(&g_cursor[d.w], 1);
    if (p0 < CAP) g_bucket[d.x * CAP + p0] = s.x;
    if (p1 < CAP) g_bucket[d.y * CAP + p1] = s.y;
    if (p2 < CAP) g_bucket[d.z * CAP + p2] = s.z;
    if (p3 < CAP) g_bucket[d.w * CAP + p3] = s.w;
}

// ---------------- GEMM + attention coefs (register-blocked 4x4) ------------
// x tile stored TRANSPOSED in smem (xsT[k][row]) so the 4 row-values per
// k-step come from ONE LDS.128 broadcast instead of 4 scalar LDS.
template <int LAYER>
__global__ __launch_bounds__(256) void k_gemm_attn(
    const float* __restrict__ xin,
    const float* __restrict__ W,
    const float* __restrict__ a_s,
    const float* __restrict__ a_d)
{
    __shared__ __align__(16) float Ws[64 * 68];
    __shared__ __align__(16) float xsT[64 * 68];   // [k][row]

    int t = threadIdx.x;
    int base = blockIdx.x * 64;

    for (int i = t; i < 1024; i += 256) {
        float4 w = *(const float4*)(W + i * 4);
        *(float4*)&Ws[(i >> 4) * 68 + (i & 15) * 4] = w;
    }
    // load x tile (coalesced) and write TRANSPOSED; ELU for layer 2; OOB -> 0
    for (int i = t; i < 1024; i += 256) {
        int row = i >> 4, c4 = i & 15;
        int grow = base + row;
        float4 v = make_float4(0.f, 0.f, 0.f, 0.f);
        if (grow < NNODES) {
            if (LAYER == 0) {
                v = *(const float4*)(xin + grow * 64 + c4 * 4);
            } else {
                float4 u = *(const float4*)&g_abuf[grow * 64 + c4 * 4];
                v = make_float4(eluf(u.x), eluf(u.y), eluf(u.z), eluf(u.w));
            }
        }
        xsT[(c4 * 4 + 0) * 68 + row] = v.x;
        xsT[(c4 * 4 + 1) * 68 + row] = v.y;
        xsT[(c4 * 4 + 2) * 68 + row] = v.z;
        xsT[(c4 * 4 + 3) * 68 + row] = v.w;
    }
    __syncthreads();

    int c  = t & 15;
    int rq = t >> 4;
    int j0 = c * 4;
    int rbase = rq * 4;

    float4 acc0 = make_float4(0.f,0.f,0.f,0.f);
    float4 acc1 = acc0, acc2 = acc0, acc3 = acc0;

    #pragma unroll 8
    for (int k = 0; k < 64; k++) {
        float4 w  = *(const float4*)&Ws[k * 68 + j0];
        float4 xv = *(const float4*)&xsT[k * 68 + rbase];   // rows rbase..rbase+3
        acc0.x += xv.x * w.x; acc0.y += xv.x * w.y; acc0.z += xv.x * w.z; acc0.w += xv.x * w.w;
        acc1.x += xv.y * w.x; acc1.y += xv.y * w.y; acc1.z += xv.y * w.z; acc1.w += xv.y * w.w;
        acc2.x += xv.z * w.x; acc2.y += xv.z * w.y; acc2.z += xv.z * w.z; acc2.w += xv.z * w.w;
        acc3.x += xv.w * w.x; acc3.y += xv.w * w.y; acc3.z += xv.w * w.z; acc3.w += xv.w * w.w;
    }

    float4 asv = *(const float4*)(a_s + j0);
    float4 adv = *(const float4*)(a_d + j0);

    float4 accs[4] = {acc0, acc1, acc2, acc3};
    #pragma unroll
    for (int i = 0; i < 4; i++) {
        int row = base + rbase + i;
        float4 a = accs[i];
        if (row < NNODES) {
            __half2 p0 = __floats2half2_rn(a.x, a.y);
            __half2 p1 = __floats2half2_rn(a.z, a.w);
            uint2 pk;
            pk.x = *(unsigned*)&p0;
            pk.y = *(unsigned*)&p1;
            *(uint2*)&g_h16[row * 32 + c * 2] = pk;
        }
        float ps = a.x * asv.x + a.y * asv.y + a.z * asv.z + a.w * asv.w;
        float pd = a.x * adv.x + a.y * adv.y + a.z * adv.z + a.w * adv.w;
        #pragma unroll
        for (int off = 8; off; off >>= 1) {
            ps += __shfl_xor_sync(0xffffffffu, ps, off);
            pd += __shfl_xor_sync(0xffffffffu, pd, off);
        }
        if (c == 0 && row < NNODES) {
            g_als[row] = ps;
            g_ald[row] = pd;
        }
    }
}

// ---------------- fused conv: 8 lanes per edge, LDG.128 gather -------------
__global__ __launch_bounds__(256) void k_conv(const float* __restrict__ bias) {
    const unsigned FULL = 0xffffffffu;
    int wid  = (blockIdx.x * 256 + threadIdx.x) >> 5;
    int lane = threadIdx.x & 31;
    if (wid >= NNODES) return;
    int grp = lane >> 3;      // 0..3: which edge of the quad
    int wi8 = lane & 7;       // feature slice: halves wi8*8 .. wi8*8+7

    int cnt = g_cursor[wid];
    cnt = cnt < CAP ? cnt : CAP;
    int r0 = wid * CAP;
    int r1 = r0 + cnt;
    float ald_d = g_ald[wid];

    float2 a0 = make_float2(0.f, 0.f), a1 = a0, a2 = a0, a3 = a0;
    float denp = 0.f;

    for (int cb = r0; cb < r1; cb += 32) {
        int e = cb + lane;
        int   s  = 0;
        float ex = 0.f;
        if (e < r1) {
            s = g_bucket[e];
            float sc = g_als[s] + ald_d;
            sc = sc > 0.f ? sc : 0.2f * sc;       // leaky relu
            ex = __expf(fminf(sc, 75.f));         // overflow guard (never hit)
        }
        denp += ex;
        int cl = (r1 - cb) < 32 ? (r1 - cb) : 32;
        #pragma unroll 4
        for (int j = 0; j < cl; j += 4) {
            int jj = j + grp;                     // <= 31 always
            int   sj  = __shfl_sync(FULL, s, jj);
            float exj = __shfl_sync(FULL, ex, jj);
            uint4 pk = *(const uint4*)&g_h16[sj * 32 + wi8 * 4];
            float2 f0 = __half22float2(*(__half2*)&pk.x);
            float2 f1 = __half22float2(*(__half2*)&pk.y);
            float2 f2 = __half22float2(*(__half2*)&pk.z);
            float2 f3 = __half22float2(*(__half2*)&pk.w);
            a0.x += exj * f0.x; a0.y += exj * f0.y;
            a1.x += exj * f1.x; a1.y += exj * f1.y;
            a2.x += exj * f2.x; a2.y += exj * f2.y;
            a3.x += exj * f3.x; a3.y += exj * f3.y;
        }
    }

    // merge the 4 edge-groups (same feature slice, disjoint edges)
    #pragma unroll
    for (int off = 8; off <= 16; off <<= 1) {
        a0.x += __shfl_xor_sync(FULL, a0.x, off);
        a0.y += __shfl_xor_sync(FULL, a0.y, off);
        a1.x += __shfl_xor_sync(FULL, a1.x, off);
        a1.y += __shfl_xor_sync(FULL, a1.y, off);
        a2.x += __shfl_xor_sync(FULL, a2.x, off);
        a2.y += __shfl_xor_sync(FULL, a2.y, off);
        a3.x += __shfl_xor_sync(FULL, a3.x, off);
        a3.y += __shfl_xor_sync(FULL, a3.y, off);
    }

    float den = denp;
    #pragma unroll
    for (int off = 16; off; off >>= 1)
        den += __shfl_xor_sync(FULL, den, off);

    if (grp == 0) {
        float inv = 1.f / den;
        float4 bv0 = *(const float4*)(bias + wi8 * 8);
        float4 bv1 = *(const float4*)(bias + wi8 * 8 + 4);
        float4 o0, o1;
        o0.x = a0.x * inv + bv0.x; o0.y = a0.y * inv + bv0.y;
        o0.z = a1.x * inv + bv0.z; o0.w = a1.y * inv + bv0.w;
        o1.x = a2.x * inv + bv1.x; o1.y = a2.y * inv + bv1.y;
        o1.z = a3.x * inv + bv1.z; o1.w = a3.y * inv + bv1.w;
        *(float4*)&g_abuf[wid * 64 + wi8 * 8]     = o0;
        *(float4*)&g_abuf[wid * 64 + wi8 * 8 + 4] = o1;
    }
}

// ---------------- MLP head + global_add_pool (j-split, low regs) -----------
__global__ __launch_bounds__(256) void k_mlp_pool(
    const float* __restrict__ mw1, const float* __restrict__ mb1,
    const float* __restrict__ mw2, const float* __restrict__ mb2,
    const int* __restrict__ batch, float* __restrict__ out)
{
    __shared__ __align__(16) float W1s[64 * 68];
    __shared__ float W2s[64 * 12];
    __shared__ float b1s[64];
    __shared__ float b2s[NCLS];

    int t = threadIdx.x;
    for (int i = t; i < 64 * 64; i += 256)
        W1s[(i >> 6) * 68 + (i & 63)] = mw1[i];
    for (int i = t; i < 64 * NCLS; i += 256)
        W2s[(i / NCLS) * 12 + (i % NCLS)] = mw2[i];
    if (t < 64)   b1s[t] = mb1[t];
    if (t < NCLS) b2s[t] = mb2[t];
    __syncthreads();

    int node = blockIdx.x * blockDim.x + t;
    bool valid = node < NNODES;

    int b = valid ? batch[node] : 0;

    float y[NCLS];
    #pragma unroll
    for (int c2 = 0; c2 < NCLS; c2++) y[c2] = valid ? b2s[c2] : 0.f;

    #pragma unroll
    for (int half = 0; half < 2; half++) {
        int jbase = half * 32;
        float z[32];
        #pragma unroll
        for (int j = 0; j < 32; j++) z[j] = 0.f;

        if (valid) {
            #pragma unroll
            for (int k4 = 0; k4 < 16; k4++) {
                float4 xv4 = *(const float4*)&g_abuf[node * 64 + k4 * 4];
                float xv[4] = {xv4.x, xv4.y, xv4.z, xv4.w};
                #pragma unroll
                for (int kk = 0; kk < 4; kk++) {
                    float xk = eluf(xv[kk]);
                    int k = k4 * 4 + kk;
                    #pragma unroll
                    for (int j = 0; j < 32; j += 4) {
                        float4 w = *(const float4*)&W1s[k * 68 + jbase + j];
                        z[j]     += xk * w.x;
                        z[j + 1] += xk * w.y;
                        z[j + 2] += xk * w.z;
                        z[j + 3] += xk * w.w;
                    }
                }
            }
            #pragma unroll
            for (int j = 0; j < 32; j++) {
                float zj = z[j] + b1s[jbase + j];
                zj = zj > 0.f ? zj : 0.f;
                #pragma unroll
                for (int c2 = 0; c2 < NCLS; c2++)
                    y[c2] += zj * W2s[(jbase + j) * 12 + c2];
            }
        }
    }

    unsigned mask = 0xffffffffu;
    int b0 = __shfl_sync(mask, b, 0);
    bool uni = __all_sync(mask, valid && (b == b0));
    if (uni) {
        #pragma unroll
        for (int c2 = 0; c2 < NCLS; c2++) {
            float v = y[c2];
            #pragma unroll
            for (int off = 16; off; off >>= 1)
                v += __shfl_xor_sync(mask, v, off);
            if ((t & 31) == 0) atomicAdd(&out[b0 * NCLS + c2], v);
        }
    } else if (valid) {
        #pragma unroll
        for (int c2 = 0; c2 < NCLS; c2++)
            atomicAdd(&out[b * NCLS + c2], y[c2]);
    }
}

// ---------------- launch ---------------------------------------------------
extern "C" void kernel_launch(void* const* d_in, const int* in_sizes, int n_in,
                              void* d_out, int out_size) {
    const float* x     = (const float*)d_in[0];
    const int*   ei    = (const int*)d_in[1];     // int32
    const int*   batch = (const int*)d_in[2];     // int32
    const float* W1  = (const float*)d_in[3];
    const float* as1 = (const float*)d_in[4];
    const float* ad1 = (const float*)d_in[5];
    const float* b1  = (const float*)d_in[6];
    const float* W2  = (const float*)d_in[7];
    const float* as2 = (const float*)d_in[8];
    const float* ad2 = (const float*)d_in[9];
    const float* b2  = (const float*)d_in[10];
    const float* mw1 = (const float*)d_in[11];
    const float* mb1 = (const float*)d_in[12];
    const float* mw2 = (const float*)d_in[13];
    const float* mb2 = (const float*)d_in[14];
    float* out = (float*)d_out;

    static cudaStream_t s2 = nullptr;
    static cudaEvent_t  eF = nullptr, eJ = nullptr;
    if (!s2) {
        cudaStreamCreateWithFlags(&s2, cudaStreamNonBlocking);
        cudaEventCreateWithFlags(&eF, cudaEventDisableTiming);
        cudaEventCreateWithFlags(&eJ, cudaEventDisableTiming);
    }

    const int TB = 256;
    int gridE4 = (NEDGES / 4 + TB - 1) / TB;      // NEDGES % 4 == 0
    int gridN  = (NNODES + TB - 1) / TB;
    int gridG  = (NNODES + 63) / 64;
    int gridC  = (NNODES * 32 + TB - 1) / TB;     // warp per node

    // fork: side stream runs GEMM-1 while stream 0 builds buckets
    cudaEventRecord(eF, 0);
    cudaStreamWaitEvent(s2, eF, 0);

    // stream 0: bucket build (no deg pass, no scan)
    k_init<<<gridN, TB>>>(out);
    k_scatter<<<gridE4, TB>>>(ei);

    // side stream: GEMM-1 (independent of buckets)
    k_gemm_attn<0><<<gridG, TB, 0, s2>>>(x, W1, as1, ad1);

    // join
    cudaEventRecord(eJ, s2);
    cudaStreamWaitEvent(0, eJ, 0);

    // conv 1
    k_conv<<<gridC, TB>>>(b1);

    // conv 2
    k_gemm_attn<1><<<gridG, TB>>>(nullptr, W2, as2, ad2);
    k_conv<<<gridC, TB>>>(b2);

    // MLP + pool
    k_mlp_pool<<<gridN, TB>>>(mw1, mb1, mw2, mb2, batch, out);
}

// round 16
// speedup vs baseline: 1.0396x; 1.0396x over previous
#include <cuda_runtime.h>
#include <cuda_fp16.h>
#include <math_constants.h>

#define NNODES 100000
#define NEDGES 1600000
#define HD     64
#define NCLS   10
#define NGRAPH 128
#define CAP    64     // bucket capacity per node (deg ~ Poisson(16); P(>63) ~ 1e-21)

// ---------------- scratch (device globals; no allocations) ----------------
__device__ __align__(16) __half2 g_h16[NNODES * 32];  // h rows, fp16 payload (128B/row)
__device__ __align__(16) float g_abuf[NNODES * HD];   // conv input / output (fp32)
__device__ float g_als[NNODES];
__device__ float g_ald[NNODES];
__device__ int   g_cursor[NNODES];                    // row length after scatter
__device__ int   g_bucket[NNODES * CAP];              // src ids, row n at n*CAP

__device__ __forceinline__ float eluf(float x) {
    return x > 0.f ? x : expm1f(x);
}

// ---------------- bucket init + out zero -----------------------------------
__global__ void k_init(float* __restrict__ out) {
    int i = blockIdx.x * blockDim.x + threadIdx.x;
    if (i < NNODES) {
        g_cursor[i] = 1;               // slot 0 = self loop
        g_bucket[i * CAP] = i;
    }
    if (i < NGRAPH * NCLS) out[i] = 0.f;
}

// ---------------- edge scatter into fixed buckets ---------------------------
// edge_index is INT32 (JAX x64 disabled downgrades jnp.int64 -> int32)
__global__ void k_scatter(const int* __restrict__ ei) {
    int i = (blockIdx.x * blockDim.x + threadIdx.x) * 4;
    if (i >= NEDGES) return;
    int4 s = *(const int4*)(ei + i);
    int4 d = *(const int4*)(ei + NEDGES + i);
    int p0 = atomicAdd(&g_cursor[d.x], 1);
    int p1 = atomicAdd(&g_cursor[d.y], 1);
    int p2 = atomicAdd(&g_cursor[d.z], 1);
    int p3 = atomicAdd(&g_cursor[d.w], 1);
    if (p0 < CAP) g_bucket[d.x * CAP + p0] = s.x;
    if (p1 < CAP) g_bucket[d.y * CAP + p1] = s.y;
    if (p2 < CAP) g_bucket[d.z * CAP + p2] = s.z;
    if (p3 < CAP) g_bucket[d.w * CAP + p3] = s.w;
}

// ---------------- GEMM + attention coefs (register-blocked 4x4) ------------
// x tile stored TRANSPOSED in smem (xsT[k][row]) so the 4 row-values per
// k-step come from ONE LDS.128 broadcast instead of 4 scalar LDS.
template <int LAYER>
__global__ __launch_bounds__(256) void k_gemm_attn(
    const float* __restrict__ xin,
    const float* __restrict__ W,
    const float* __restrict__ a_s,
    const float* __restrict__ a_d)
{
    __shared__ __align__(16) float Ws[64 * 68];
    __shared__ __align__(16) float xsT[64 * 68];   // [k][row]

    int t = threadIdx.x;
    int base = blockIdx.x * 64;

    for (int i = t; i < 1024; i += 256) {
        float4 w = *(const float4*)(W + i * 4);
        *(float4*)&Ws[(i >> 4) * 68 + (i & 15) * 4] = w;
    }
    // load x tile (coalesced) and write TRANSPOSED; ELU for layer 2; OOB -> 0
    for (int i = t; i < 1024; i += 256) {
        int row = i >> 4, c4 = i & 15;
        int grow = base + row;
        float4 v = make_float4(0.f, 0.f, 0.f, 0.f);
        if (grow < NNODES) {
            if (LAYER == 0) {
                v = *(const float4*)(xin + grow * 64 + c4 * 4);
            } else {
                float4 u = *(const float4*)&g_abuf[grow * 64 + c4 * 4];
                v = make_float4(eluf(u.x), eluf(u.y), eluf(u.z), eluf(u.w));
            }
        }
        xsT[(c4 * 4 + 0) * 68 + row] = v.x;
        xsT[(c4 * 4 + 1) * 68 + row] = v.y;
        xsT[(c4 * 4 + 2) * 68 + row] = v.z;
        xsT[(c4 * 4 + 3) * 68 + row] = v.w;
    }
    __syncthreads();

    int c  = t & 15;
    int rq = t >> 4;
    int j0 = c * 4;
    int rbase = rq * 4;

    float4 acc0 = make_float4(0.f,0.f,0.f,0.f);
    float4 acc1 = acc0, acc2 = acc0, acc3 = acc0;

    #pragma unroll 8
    for (int k = 0; k < 64; k++) {
        float4 w  = *(const float4*)&Ws[k * 68 + j0];
        float4 xv = *(const float4*)&xsT[k * 68 + rbase];   // rows rbase..rbase+3
        acc0.x += xv.x * w.x; acc0.y += xv.x * w.y; acc0.z += xv.x * w.z; acc0.w += xv.x * w.w;
        acc1.x += xv.y * w.x; acc1.y += xv.y * w.y; acc1.z += xv.y * w.z; acc1.w += xv.y * w.w;
        acc2.x += xv.z * w.x; acc2.y += xv.z * w.y; acc2.z += xv.z * w.z; acc2.w += xv.z * w.w;
        acc3.x += xv.w * w.x; acc3.y += xv.w * w.y; acc3.z += xv.w * w.z; acc3.w += xv.w * w.w;
    }

    float4 asv = *(const float4*)(a_s + j0);
    float4 adv = *(const float4*)(a_d + j0);

    float4 accs[4] = {acc0, acc1, acc2, acc3};
    #pragma unroll
    for (int i = 0; i < 4; i++) {
        int row = base + rbase + i;
        float4 a = accs[i];
        if (row < NNODES) {
            __half2 p0 = __floats2half2_rn(a.x, a.y);
            __half2 p1 = __floats2half2_rn(a.z, a.w);
            uint2 pk;
            pk.x = *(unsigned*)&p0;
            pk.y = *(unsigned*)&p1;
            *(uint2*)&g_h16[row * 32 + c * 2] = pk;
        }
        float ps = a.x * asv.x + a.y * asv.y + a.z * asv.z + a.w * asv.w;
        float pd = a.x * adv.x + a.y * adv.y + a.z * adv.z + a.w * adv.w;
        #pragma unroll
        for (int off = 8; off; off >>= 1) {
            ps += __shfl_xor_sync(0xffffffffu, ps, off);
            pd += __shfl_xor_sync(0xffffffffu, pd, off);
        }
        if (c == 0 && row < NNODES) {
            g_als[row] = ps;
            g_ald[row] = pd;
        }
    }
}

// ---------------- fused conv: 8 lanes per edge, LDG.128 gather -------------
// (R14 version: unroll 2 keeps regs at 32 and occupancy at ~84%.)
__global__ __launch_bounds__(256) void k_conv(const float* __restrict__ bias) {
    const unsigned FULL = 0xffffffffu;
    int wid  = (blockIdx.x * 256 + threadIdx.x) >> 5;
    int lane = threadIdx.x & 31;
    if (wid >= NNODES) return;
    int grp = lane >> 3;      // 0..3: which edge of the quad
    int wi8 = lane & 7;       // feature slice: halves wi8*8 .. wi8*8+7

    int cnt = g_cursor[wid];
    cnt = cnt < CAP ? cnt : CAP;
    int r0 = wid * CAP;
    int r1 = r0 + cnt;
    float ald_d = g_ald[wid];

    float2 a0 = make_float2(0.f, 0.f), a1 = a0, a2 = a0, a3 = a0;
    float denp = 0.f;

    for (int cb = r0; cb < r1; cb += 32) {
        int e = cb + lane;
        int   s  = 0;
        float ex = 0.f;
        if (e < r1) {
            s = g_bucket[e];
            float sc = g_als[s] + ald_d;
            sc = sc > 0.f ? sc : 0.2f * sc;       // leaky relu
            ex = __expf(fminf(sc, 75.f));         // overflow guard (never hit)
        }
        denp += ex;
        int cl = (r1 - cb) < 32 ? (r1 - cb) : 32;
        #pragma unroll 2
        for (int j = 0; j < cl; j += 4) {
            int jj = j + grp;                     // <= 31 always
            int   sj  = __shfl_sync(FULL, s, jj);
            float exj = __shfl_sync(FULL, ex, jj);
            uint4 pk = *(const uint4*)&g_h16[sj * 32 + wi8 * 4];
            float2 f0 = __half22float2(*(__half2*)&pk.x);
            float2 f1 = __half22float2(*(__half2*)&pk.y);
            float2 f2 = __half22float2(*(__half2*)&pk.z);
            float2 f3 = __half22float2(*(__half2*)&pk.w);
            a0.x += exj * f0.x; a0.y += exj * f0.y;
            a1.x += exj * f1.x; a1.y += exj * f1.y;
            a2.x += exj * f2.x; a2.y += exj * f2.y;
            a3.x += exj * f3.x; a3.y += exj * f3.y;
        }
    }

    // merge the 4 edge-groups (same feature slice, disjoint edges)
    #pragma unroll
    for (int off = 8; off <= 16; off <<= 1) {
        a0.x += __shfl_xor_sync(FULL, a0.x, off);
        a0.y += __shfl_xor_sync(FULL, a0.y, off);
        a1.x += __shfl_xor_sync(FULL, a1.x, off);
        a1.y += __shfl_xor_sync(FULL, a1.y, off);
        a2.x += __shfl_xor_sync(FULL, a2.x, off);
        a2.y += __shfl_xor_sync(FULL, a2.y, off);
        a3.x += __shfl_xor_sync(FULL, a3.x, off);
        a3.y += __shfl_xor_sync(FULL, a3.y, off);
    }

    float den = denp;
    #pragma unroll
    for (int off = 16; off; off >>= 1)
        den += __shfl_xor_sync(FULL, den, off);

    if (grp == 0) {
        float inv = 1.f / den;
        float4 bv0 = *(const float4*)(bias + wi8 * 8);
        float4 bv1 = *(const float4*)(bias + wi8 * 8 + 4);
        float4 o0, o1;
        o0.x = a0.x * inv + bv0.x; o0.y = a0.y * inv + bv0.y;
        o0.z = a1.x * inv + bv0.z; o0.w = a1.y * inv + bv0.w;
        o1.x = a2.x * inv + bv1.x; o1.y = a2.y * inv + bv1.y;
        o1.z = a3.x * inv + bv1.z; o1.w = a3.y * inv + bv1.w;
        *(float4*)&g_abuf[wid * 64 + wi8 * 8]     = o0;
        *(float4*)&g_abuf[wid * 64 + wi8 * 8 + 4] = o1;
    }
}

// ---------------- MLP head + global_add_pool (j-split, low regs) -----------
__global__ __launch_bounds__(256) void k_mlp_pool(
    const float* __restrict__ mw1, const float* __restrict__ mb1,
    const float* __restrict__ mw2, const float* __restrict__ mb2,
    const int* __restrict__ batch, float* __restrict__ out)
{
    __shared__ __align__(16) float W1s[64 * 68];
    __shared__ float W2s[64 * 12];
    __shared__ float b1s[64];
    __shared__ float b2s[NCLS];

    int t = threadIdx.x;
    for (int i = t; i < 64 * 64; i += 256)
        W1s[(i >> 6) * 68 + (i & 63)] = mw1[i];
    for (int i = t; i < 64 * NCLS; i += 256)
        W2s[(i / NCLS) * 12 + (i % NCLS)] = mw2[i];
    if (t < 64)   b1s[t] = mb1[t];
    if (t < NCLS) b2s[t] = mb2[t];
    __syncthreads();

    int node = blockIdx.x * blockDim.x + t;
    bool valid = node < NNODES;

    int b = valid ? batch[node] : 0;

    float y[NCLS];
    #pragma unroll
    for (int c2 = 0; c2 < NCLS; c2++) y[c2] = valid ? b2s[c2] : 0.f;

    #pragma unroll
    for (int half = 0; half < 2; half++) {
        int jbase = half * 32;
        float z[32];
        #pragma unroll
        for (int j = 0; j < 32; j++) z[j] = 0.f;

        if (valid) {
            #pragma unroll
            for (int k4 = 0; k4 < 16; k4++) {
                float4 xv4 = *(const float4*)&g_abuf[node * 64 + k4 * 4];
                float xv[4] = {xv4.x, xv4.y, xv4.z, xv4.w};
                #pragma unroll
                for (int kk = 0; kk < 4; kk++) {
                    float xk = eluf(xv[kk]);
                    int k = k4 * 4 + kk;
                    #pragma unroll
                    for (int j = 0; j < 32; j += 4) {
                        float4 w = *(const float4*)&W1s[k * 68 + jbase + j];
                        z[j]     += xk * w.x;
                        z[j + 1] += xk * w.y;
                        z[j + 2] += xk * w.z;
                        z[j + 3] += xk * w.w;
                    }
                }
            }
            #pragma unroll
            for (int j = 0; j < 32; j++) {
                float zj = z[j] + b1s[jbase + j];
                zj = zj > 0.f ? zj : 0.f;
                #pragma unroll
                for (int c2 = 0; c2 < NCLS; c2++)
                    y[c2] += zj * W2s[(jbase + j) * 12 + c2];
            }
        }
    }

    unsigned mask = 0xffffffffu;
    int b0 = __shfl_sync(mask, b, 0);
    bool uni = __all_sync(mask, valid && (b == b0));
    if (uni) {
        #pragma unroll
        for (int c2 = 0; c2 < NCLS; c2++) {
            float v = y[c2];
            #pragma unroll
            for (int off = 16; off; off >>= 1)
                v += __shfl_xor_sync(mask, v, off);
            if ((t & 31) == 0) atomicAdd(&out[b0 * NCLS + c2], v);
        }
    } else if (valid) {
        #pragma unroll
        for (int c2 = 0; c2 < NCLS; c2++)
            atomicAdd(&out[b * NCLS + c2], y[c2]);
    }
}

// ---------------- launch ---------------------------------------------------
extern "C" void kernel_launch(void* const* d_in, const int* in_sizes, int n_in,
                              void* d_out, int out_size) {
    const float* x     = (const float*)d_in[0];
    const int*   ei    = (const int*)d_in[1];     // int32
    const int*   batch = (const int*)d_in[2];     // int32
    const float* W1  = (const float*)d_in[3];
    const float* as1 = (const float*)d_in[4];
    const float* ad1 = (const float*)d_in[5];
    const float* b1  = (const float*)d_in[6];
    const float* W2  = (const float*)d_in[7];
    const float* as2 = (const float*)d_in[8];
    const float* ad2 = (const float*)d_in[9];
    const float* b2  = (const float*)d_in[10];
    const float* mw1 = (const float*)d_in[11];
    const float* mb1 = (const float*)d_in[12];
    const float* mw2 = (const float*)d_in[13];
    const float* mb2 = (const float*)d_in[14];
    float* out = (float*)d_out;

    static cudaStream_t s2 = nullptr;
    static cudaEvent_t  eF = nullptr, eJ = nullptr;
    if (!s2) {
        cudaStreamCreateWithFlags(&s2, cudaStreamNonBlocking);
        cudaEventCreateWithFlags(&eF, cudaEventDisableTiming);
        cudaEventCreateWithFlags(&eJ, cudaEventDisableTiming);
    }

    const int TB = 256;
    int gridE4 = (NEDGES / 4 + TB - 1) / TB;      // NEDGES % 4 == 0
    int gridN  = (NNODES + TB - 1) / TB;
    int gridG  = (NNODES + 63) / 64;
    int gridC  = (NNODES * 32 + TB - 1) / TB;     // warp per node

    // fork: side stream runs GEMM-1 while stream 0 builds buckets
    cudaEventRecord(eF, 0);
    cudaStreamWaitEvent(s2, eF, 0);

    // stream 0: bucket build (no deg pass, no scan)
    k_init<<<gridN, TB>>>(out);
    k_scatter<<<gridE4, TB>>>(ei);

    // side stream: GEMM-1 (independent of buckets)
    k_gemm_attn<0><<<gridG, TB, 0, s2>>>(x, W1, as1, ad1);

    // join
    cudaEventRecord(eJ, s2);
    cudaStreamWaitEvent(0, eJ, 0);

    // conv 1
    k_conv<<<gridC, TB>>>(b1);

    // conv 2
    k_gemm_attn<1><<<gridG, TB>>>(nullptr, W2, as2, ad2);
    k_conv<<<gridC, TB>>>(b2);

    // MLP + pool
    k_mlp_pool<<<gridN, TB>>>(mw1, mb1, mw2, mb2, batch, out);
}

// round 17
// speedup vs baseline: 1.0536x; 1.0136x over previous
#include <cuda_runtime.h>
#include <cuda_fp16.h>
#include <math_constants.h>
#include <mma.h>

using namespace nvcuda;

#define NNODES 100000
#define NEDGES 1600000
#define HD     64
#define NCLS   10
#define NGRAPH 128
#define CAP    64     // bucket capacity per node (deg ~ Poisson(16); P(>63) ~ 1e-21)

// ---------------- scratch (device globals; no allocations) ----------------
__device__ __align__(16) __half2 g_h16[NNODES * 32];  // h rows, fp16 payload (128B/row)
__device__ __align__(16) float g_abuf[NNODES * HD];   // conv input / output (fp32)
__device__ float g_als[NNODES];
__device__ float g_ald[NNODES];
__device__ int   g_cursor[NNODES];                    // row length after scatter
__device__ int   g_bucket[NNODES * CAP];              // src ids, row n at n*CAP

__device__ __forceinline__ float eluf(float x) {
    return x > 0.f ? x : expm1f(x);
}

// ---------------- bucket init + out zero -----------------------------------
__global__ void k_init(float* __restrict__ out) {
    int i = blockIdx.x * blockDim.x + threadIdx.x;
    if (i < NNODES) {
        g_cursor[i] = 1;               // slot 0 = self loop
        g_bucket[i * CAP] = i;
    }
    if (i < NGRAPH * NCLS) out[i] = 0.f;
}

// ---------------- edge scatter into fixed buckets ---------------------------
// edge_index is INT32 (JAX x64 disabled downgrades jnp.int64 -> int32)
__global__ void k_scatter(const int* __restrict__ ei) {
    int i = (blockIdx.x * blockDim.x + threadIdx.x) * 4;
    if (i >= NEDGES) return;
    int4 s = *(const int4*)(ei + i);
    int4 d = *(const int4*)(ei + NEDGES + i);
    int p0 = atomicAdd(&g_cursor[d.x], 1);
    int p1 = atomicAdd(&g_cursor[d.y], 1);
    int p2 = atomicAdd(&g_cursor[d.z], 1);
    int p3 = atomicAdd(&g_cursor[d.w], 1);
    if (p0 < CAP) g_bucket[d.x * CAP + p0] = s.x;
    if (p1 < CAP) g_bucket[d.y * CAP + p1] = s.y;
    if (p2 < CAP) g_bucket[d.z * CAP + p2] = s.z;
    if (p3 < CAP) g_bucket[d.w * CAP + p3] = s.w;
}

// ---------------- GEMM + attention coefs (WMMA tf32 tensor cores) ----------
// 64x64x64 tile per block. 8 warps; warp w owns m-tile (w>>1), n-tiles
// {2*(w&1), 2*(w&1)+1} (16x32 strip). K loop = 8 steps of k=8. After the
// K loop the x buffer is reused for the fp32 result tile (keeps smem 34.8KB).
template <int LAYER>
__global__ __launch_bounds__(256) void k_gemm_attn(
    const float* __restrict__ xin,
    const float* __restrict__ W,
    const float* __restrict__ a_s,
    const float* __restrict__ a_d)
{
    __shared__ __align__(32) float Ws[64 * 68];   // W[k][n], pad 68
    __shared__ __align__(32) float xs[64 * 68];   // x[row][k]; reused for h[row][n]

    int t = threadIdx.x;
    int base = blockIdx.x * 64;

    for (int i = t; i < 1024; i += 256) {
        float4 w = *(const float4*)(W + i * 4);
        *(float4*)&Ws[(i >> 4) * 68 + (i & 15) * 4] = w;
    }
    // load x tile row-major [row][k]; ELU for layer 2; OOB rows -> 0
    for (int i = t; i < 1024; i += 256) {
        int row = i >> 4, c4 = i & 15;
        int grow = base + row;
        float4 v = make_float4(0.f, 0.f, 0.f, 0.f);
        if (grow < NNODES) {
            if (LAYER == 0) {
                v = *(const float4*)(xin + grow * 64 + c4 * 4);
            } else {
                float4 u = *(const float4*)&g_abuf[grow * 64 + c4 * 4];
                v = make_float4(eluf(u.x), eluf(u.y), eluf(u.z), eluf(u.w));
            }
        }
        *(float4*)&xs[row * 68 + c4 * 4] = v;
    }
    __syncthreads();

    int warp = t >> 5;
    int mt   = warp >> 1;            // 0..3  (16-row tile)
    int nt0  = (warp & 1) * 2;       // 0 or 2 (first of two 16-col tiles)

    wmma::fragment<wmma::accumulator, 16, 16, 8, float> c0, c1;
    wmma::fill_fragment(c0, 0.f);
    wmma::fill_fragment(c1, 0.f);

    #pragma unroll
    for (int ks = 0; ks < 8; ks++) {
        wmma::fragment<wmma::matrix_a, 16, 16, 8, wmma::precision::tf32, wmma::row_major> af;
        wmma::load_matrix_sync(af, &xs[mt * 16 * 68 + ks * 8], 68);
        #pragma unroll
        for (int i = 0; i < af.num_elements; i++)
            af.x[i] = wmma::__float_to_tf32(af.x[i]);

        wmma::fragment<wmma::matrix_b, 16, 16, 8, wmma::precision::tf32, wmma::row_major> bf0, bf1;
        wmma::load_matrix_sync(bf0, &Ws[ks * 8 * 68 + nt0 * 16], 68);
        wmma::load_matrix_sync(bf1, &Ws[ks * 8 * 68 + (nt0 + 1) * 16], 68);
        #pragma unroll
        for (int i = 0; i < bf0.num_elements; i++) {
            bf0.x[i] = wmma::__float_to_tf32(bf0.x[i]);
            bf1.x[i] = wmma::__float_to_tf32(bf1.x[i]);
        }
        wmma::mma_sync(c0, af, bf0, c0);
        wmma::mma_sync(c1, af, bf1, c1);
    }

    __syncthreads();   // all A-tile reads done; reuse xs for the result
    wmma::store_matrix_sync(&xs[mt * 16 * 68 + nt0 * 16],       c0, 68, wmma::mem_row_major);
    wmma::store_matrix_sync(&xs[mt * 16 * 68 + (nt0 + 1) * 16], c1, 68, wmma::mem_row_major);
    __syncthreads();

    // epilogue: fp16 payload + attention halves (reads h rows from xs)
    int c  = t & 15;
    int rq = t >> 4;
    int j0 = c * 4;
    int rbase = rq * 4;

    float4 asv = *(const float4*)(a_s + j0);
    float4 adv = *(const float4*)(a_d + j0);

    #pragma unroll
    for (int i = 0; i < 4; i++) {
        int row = base + rbase + i;
        float4 a = *(const float4*)&xs[(rbase + i) * 68 + j0];
        if (row < NNODES) {
            __half2 p0 = __floats2half2_rn(a.x, a.y);
            __half2 p1 = __floats2half2_rn(a.z, a.w);
            uint2 pk;
            pk.x = *(unsigned*)&p0;
            pk.y = *(unsigned*)&p1;
            *(uint2*)&g_h16[row * 32 + c * 2] = pk;
        }
        float ps = a.x * asv.x + a.y * asv.y + a.z * asv.z + a.w * asv.w;
        float pd = a.x * adv.x + a.y * adv.y + a.z * adv.z + a.w * adv.w;
        #pragma unroll
        for (int off = 8; off; off >>= 1) {
            ps += __shfl_xor_sync(0xffffffffu, ps, off);
            pd += __shfl_xor_sync(0xffffffffu, pd, off);
        }
        if (c == 0 && row < NNODES) {
            g_als[row] = ps;
            g_ald[row] = pd;
        }
    }
}

// ---------------- fused conv: 8 lanes per edge, LDG.128 gather -------------
__global__ __launch_bounds__(256) void k_conv(const float* __restrict__ bias) {
    const unsigned FULL = 0xffffffffu;
    int wid  = (blockIdx.x * 256 + threadIdx.x) >> 5;
    int lane = threadIdx.x & 31;
    if (wid >= NNODES) return;
    int grp = lane >> 3;      // 0..3: which edge of the quad
    int wi8 = lane & 7;       // feature slice: halves wi8*8 .. wi8*8+7

    int cnt = g_cursor[wid];
    cnt = cnt < CAP ? cnt : CAP;
    int r0 = wid * CAP;
    int r1 = r0 + cnt;
    float ald_d = g_ald[wid];

    float2 a0 = make_float2(0.f, 0.f), a1 = a0, a2 = a0, a3 = a0;
    float denp = 0.f;

    for (int cb = r0; cb < r1; cb += 32) {
        int e = cb + lane;
        int   s  = 0;
        float ex = 0.f;
        if (e < r1) {
            s = g_bucket[e];
            float sc = g_als[s] + ald_d;
            sc = sc > 0.f ? sc : 0.2f * sc;       // leaky relu
            ex = __expf(fminf(sc, 75.f));         // overflow guard (never hit)
        }
        denp += ex;
        int cl = (r1 - cb) < 32 ? (r1 - cb) : 32;
        #pragma unroll 2
        for (int j = 0; j < cl; j += 4) {
            int jj = j + grp;                     // <= 31 always
            int   sj  = __shfl_sync(FULL, s, jj);
            float exj = __shfl_sync(FULL, ex, jj);
            uint4 pk = *(const uint4*)&g_h16[sj * 32 + wi8 * 4];
            float2 f0 = __half22float2(*(__half2*)&pk.x);
            float2 f1 = __half22float2(*(__half2*)&pk.y);
            float2 f2 = __half22float2(*(__half2*)&pk.z);
            float2 f3 = __half22float2(*(__half2*)&pk.w);
            a0.x += exj * f0.x; a0.y += exj * f0.y;
            a1.x += exj * f1.x; a1.y += exj * f1.y;
            a2.x += exj * f2.x; a2.y += exj * f2.y;
            a3.x += exj * f3.x; a3.y += exj * f3.y;
        }
    }

    // merge the 4 edge-groups (same feature slice, disjoint edges)
    #pragma unroll
    for (int off = 8; off <= 16; off <<= 1) {
        a0.x += __shfl_xor_sync(FULL, a0.x, off);
        a0.y += __shfl_xor_sync(FULL, a0.y, off);
        a1.x += __shfl_xor_sync(FULL, a1.x, off);
        a1.y += __shfl_xor_sync(FULL, a1.y, off);
        a2.x += __shfl_xor_sync(FULL, a2.x, off);
        a2.y += __shfl_xor_sync(FULL, a2.y, off);
        a3.x += __shfl_xor_sync(FULL, a3.x, off);
        a3.y += __shfl_xor_sync(FULL, a3.y, off);
    }

    float den = denp;
    #pragma unroll
    for (int off = 16; off; off >>= 1)
        den += __shfl_xor_sync(FULL, den, off);

    if (grp == 0) {
        float inv = 1.f / den;
        float4 bv0 = *(const float4*)(bias + wi8 * 8);
        float4 bv1 = *(const float4*)(bias + wi8 * 8 + 4);
        float4 o0, o1;
        o0.x = a0.x * inv + bv0.x; o0.y = a0.y * inv + bv0.y;
        o0.z = a1.x * inv + bv0.z; o0.w = a1.y * inv + bv0.w;
        o1.x = a2.x * inv + bv1.x; o1.y = a2.y * inv + bv1.y;
        o1.z = a3.x * inv + bv1.z; o1.w = a3.y * inv + bv1.w;
        *(float4*)&g_abuf[wid * 64 + wi8 * 8]     = o0;
        *(float4*)&g_abuf[wid * 64 + wi8 * 8 + 4] = o1;
    }
}

// ---------------- MLP head + global_add_pool (j-split, low regs) -----------
__global__ __launch_bounds__(256) void k_mlp_pool(
    const float* __restrict__ mw1, const float* __restrict__ mb1,
    const float* __restrict__ mw2, const float* __restrict__ mb2,
    const int* __restrict__ batch, float* __restrict__ out)
{
    __shared__ __align__(16) float W1s[64 * 68];
    __shared__ float W2s[64 * 12];
    __shared__ float b1s[64];
    __shared__ float b2s[NCLS];

    int t = threadIdx.x;
    for (int i = t; i < 64 * 64; i += 256)
        W1s[(i >> 6) * 68 + (i & 63)] = mw1[i];
    for (int i = t; i < 64 * NCLS; i += 256)
        W2s[(i / NCLS) * 12 + (i % NCLS)] = mw2[i];
    if (t < 64)   b1s[t] = mb1[t];
    if (t < NCLS) b2s[t] = mb2[t];
    __syncthreads();

    int node = blockIdx.x * blockDim.x + t;
    bool valid = node < NNODES;

    int b = valid ? batch[node] : 0;

    float y[NCLS];
    #pragma unroll
    for (int c2 = 0; c2 < NCLS; c2++) y[c2] = valid ? b2s[c2] : 0.f;

    #pragma unroll
    for (int half = 0; half < 2; half++) {
        int jbase = half * 32;
        float z[32];
        #pragma unroll
        for (int j = 0; j < 32; j++) z[j] = 0.f;

        if (valid) {
            #pragma unroll
            for (int k4 = 0; k4 < 16; k4++) {
                float4 xv4 = *(const float4*)&g_abuf[node * 64 + k4 * 4];
                float xv[4] = {xv4.x, xv4.y, xv4.z, xv4.w};
                #pragma unroll
                for (int kk = 0; kk < 4; kk++) {
                    float xk = eluf(xv[kk]);
                    int k = k4 * 4 + kk;
                    #pragma unroll
                    for (int j = 0; j < 32; j += 4) {
                        float4 w = *(const float4*)&W1s[k * 68 + jbase + j];
                        z[j]     += xk * w.x;
                        z[j + 1] += xk * w.y;
                        z[j + 2] += xk * w.z;
                        z[j + 3] += xk * w.w;
                    }
                }
            }
            #pragma unroll
            for (int j = 0; j < 32; j++) {
                float zj = z[j] + b1s[jbase + j];
                zj = zj > 0.f ? zj : 0.f;
                #pragma unroll
                for (int c2 = 0; c2 < NCLS; c2++)
                    y[c2] += zj * W2s[(jbase + j) * 12 + c2];
            }
        }
    }

    unsigned mask = 0xffffffffu;
    int b0 = __shfl_sync(mask, b, 0);
    bool uni = __all_sync(mask, valid && (b == b0));
    if (uni) {
        #pragma unroll
        for (int c2 = 0; c2 < NCLS; c2++) {
            float v = y[c2];
            #pragma unroll
            for (int off = 16; off; off >>= 1)
                v += __shfl_xor_sync(mask, v, off);
            if ((t & 31) == 0) atomicAdd(&out[b0 * NCLS + c2], v);
        }
    } else if (valid) {
        #pragma unroll
        for (int c2 = 0; c2 < NCLS; c2++)
            atomicAdd(&out[b * NCLS + c2], y[c2]);
    }
}

// ---------------- launch ---------------------------------------------------
extern "C" void kernel_launch(void* const* d_in, const int* in_sizes, int n_in,
                              void* d_out, int out_size) {
    const float* x     = (const float*)d_in[0];
    const int*   ei    = (const int*)d_in[1];     // int32
    const int*   batch = (const int*)d_in[2];     // int32
    const float* W1  = (const float*)d_in[3];
    const float* as1 = (const float*)d_in[4];
    const float* ad1 = (const float*)d_in[5];
    const float* b1  = (const float*)d_in[6];
    const float* W2  = (const float*)d_in[7];
    const float* as2 = (const float*)d_in[8];
    const float* ad2 = (const float*)d_in[9];
    const float* b2  = (const float*)d_in[10];
    const float* mw1 = (const float*)d_in[11];
    const float* mb1 = (const float*)d_in[12];
    const float* mw2 = (const float*)d_in[13];
    const float* mb2 = (const float*)d_in[14];
    float* out = (float*)d_out;

    static cudaStream_t s2 = nullptr;
    static cudaEvent_t  eF = nullptr, eJ = nullptr;
    if (!s2) {
        cudaStreamCreateWithFlags(&s2, cudaStreamNonBlocking);
        cudaEventCreateWithFlags(&eF, cudaEventDisableTiming);
        cudaEventCreateWithFlags(&eJ, cudaEventDisableTiming);
    }

    const int TB = 256;
    int gridE4 = (NEDGES / 4 + TB - 1) / TB;      // NEDGES % 4 == 0
    int gridN  = (NNODES + TB - 1) / TB;
    int gridG  = (NNODES + 63) / 64;
    int gridC  = (NNODES * 32 + TB - 1) / TB;     // warp per node

    // fork: side stream runs GEMM-1 while stream 0 builds buckets
    cudaEventRecord(eF, 0);
    cudaStreamWaitEvent(s2, eF, 0);

    // stream 0: bucket build (no deg pass, no scan)
    k_init<<<gridN, TB>>>(out);
    k_scatter<<<gridE4, TB>>>(ei);

    // side stream: GEMM-1 (independent of buckets)
    k_gemm_attn<0><<<gridG, TB, 0, s2>>>(x, W1, as1, ad1);

    // join
    cudaEventRecord(eJ, s2);
    cudaStreamWaitEvent(0, eJ, 0);

    // conv 1
    k_conv<<<gridC, TB>>>(b1);

    // conv 2
    k_gemm_attn<1><<<gridG, TB>>>(nullptr, W2, as2, ad2);
    k_conv<<<gridC, TB>>>(b2);

    // MLP + pool
    k_mlp_pool<<<gridN, TB>>>(mw1, mb1, mw2, mb2, batch, out);
}